// round 1
// baseline (speedup 1.0000x reference)
#include <cuda_runtime.h>
#include <cstdint>

// Problem shapes (fixed by the reference setup_inputs)
static constexpr int Bb = 8, Tt = 256, Uu = 64, Dd = 512, Aa = 256, Vv = 1024;
static constexpr long long Mm = (long long)Bb * Tt * Uu;   // 131072

// Tiling
#define BM 128
#define BN 128
#define BK 16
#define SM_LD 132   // padded leading dim for smem tiles (kills store bank conflicts)

// NT GEMM: C[m,n] = sum_k A[m,k] * B[n,k]
//   A: M x K row-major (K contiguous), B: N x K row-major (K contiguous)
// Epilogue selected at compile time:
//   FUSE=1: C = relu(acc + src[b,t,n] + tgt[b,u,n] + bias[n])   (activation kernel)
//   FUSE=0: C = acc + bias[n]                                    (output kernel)
template <int K, int FUSE>
__global__ __launch_bounds__(256, 2)
void gemm_nt_kernel(const float* __restrict__ Ag,
                    const float* __restrict__ Bg,
                    const float* __restrict__ bias,
                    const float* __restrict__ src,   // (B*T, D) — used when FUSE
                    const float* __restrict__ tgt,   // (B*U, D) — used when FUSE
                    float* __restrict__ Cg,
                    int N)
{
    __shared__ float As[BK][SM_LD];
    __shared__ float Bs[BK][SM_LD];

    const int m0 = blockIdx.y * BM;
    const int n0 = blockIdx.x * BN;
    const int tid = threadIdx.x;
    const int tx = tid & 15;        // 0..15 -> N direction
    const int ty = tid >> 4;        // 0..15 -> M direction

    // Load mapping: 128 rows x 16 cols tile = 512 float4 slots, 2 per thread.
    const int lrow = tid >> 2;          // 0..63
    const int lcol = (tid & 3) * 4;     // 0,4,8,12

    float acc[8][8];
#pragma unroll
    for (int i = 0; i < 8; i++)
#pragma unroll
        for (int j = 0; j < 8; j++) acc[i][j] = 0.0f;

    const float* Ap0 = Ag + (long long)(m0 + lrow) * K + lcol;
    const float* Ap1 = Ag + (long long)(m0 + lrow + 64) * K + lcol;
    const float* Bp0 = Bg + (long long)(n0 + lrow) * K + lcol;
    const float* Bp1 = Bg + (long long)(n0 + lrow + 64) * K + lcol;

    for (int kb = 0; kb < K; kb += BK) {
        float4 a0 = *(const float4*)(Ap0 + kb);
        float4 a1 = *(const float4*)(Ap1 + kb);
        float4 b0 = *(const float4*)(Bp0 + kb);
        float4 b1 = *(const float4*)(Bp1 + kb);

        As[lcol + 0][lrow] = a0.x; As[lcol + 1][lrow] = a0.y;
        As[lcol + 2][lrow] = a0.z; As[lcol + 3][lrow] = a0.w;
        As[lcol + 0][lrow + 64] = a1.x; As[lcol + 1][lrow + 64] = a1.y;
        As[lcol + 2][lrow + 64] = a1.z; As[lcol + 3][lrow + 64] = a1.w;

        Bs[lcol + 0][lrow] = b0.x; Bs[lcol + 1][lrow] = b0.y;
        Bs[lcol + 2][lrow] = b0.z; Bs[lcol + 3][lrow] = b0.w;
        Bs[lcol + 0][lrow + 64] = b1.x; Bs[lcol + 1][lrow + 64] = b1.y;
        Bs[lcol + 2][lrow + 64] = b1.z; Bs[lcol + 3][lrow + 64] = b1.w;

        __syncthreads();

#pragma unroll
        for (int k = 0; k < BK; k++) {
            float a[8], b[8];
            *(float4*)&a[0] = *(const float4*)&As[k][ty * 4];
            *(float4*)&a[4] = *(const float4*)&As[k][ty * 4 + 64];
            *(float4*)&b[0] = *(const float4*)&Bs[k][tx * 4];
            *(float4*)&b[4] = *(const float4*)&Bs[k][tx * 4 + 64];
#pragma unroll
            for (int i = 0; i < 8; i++)
#pragma unroll
                for (int j = 0; j < 8; j++)
                    acc[i][j] += a[i] * b[j];
        }
        __syncthreads();
    }

    // Epilogue (vectorized along n: j blocks of 4 contiguous columns)
#pragma unroll
    for (int i = 0; i < 8; i++) {
        const int m = m0 + ((i < 4) ? (ty * 4 + i) : (64 + ty * 4 + (i - 4)));
        const float* srow = nullptr;
        const float* trow = nullptr;
        if (FUSE) {
            const int bi = m / (Tt * Uu);
            const int r  = m % (Tt * Uu);
            const int ti = r / Uu;
            const int ui = r % Uu;
            srow = src + ((long long)(bi * Tt + ti)) * Dd;
            trow = tgt + ((long long)(bi * Uu + ui)) * Dd;
        }
#pragma unroll
        for (int jj = 0; jj < 2; jj++) {
            const int n = n0 + tx * 4 + jj * 64;
            float4 bi4 = *(const float4*)(bias + n);
            float4 o;
            if (FUSE) {
                float4 s4 = *(const float4*)(srow + n);
                float4 t4 = *(const float4*)(trow + n);
                o.x = fmaxf(acc[i][jj * 4 + 0] + s4.x + t4.x + bi4.x, 0.0f);
                o.y = fmaxf(acc[i][jj * 4 + 1] + s4.y + t4.y + bi4.y, 0.0f);
                o.z = fmaxf(acc[i][jj * 4 + 2] + s4.z + t4.z + bi4.z, 0.0f);
                o.w = fmaxf(acc[i][jj * 4 + 3] + s4.w + t4.w + bi4.w, 0.0f);
            } else {
                o.x = acc[i][jj * 4 + 0] + bi4.x;
                o.y = acc[i][jj * 4 + 1] + bi4.y;
                o.z = acc[i][jj * 4 + 2] + bi4.z;
                o.w = acc[i][jj * 4 + 3] + bi4.w;
            }
            *(float4*)(Cg + (long long)m * N + n) = o;
        }
    }
}

// Pass-through of lengths, converted to the float32 output dtype.
__global__ void lengths_kernel(const int* __restrict__ sl,
                               const int* __restrict__ tl,
                               float* __restrict__ out_sl,
                               float* __restrict__ out_tl)
{
    int i = threadIdx.x;
    if (i < Bb) {
        out_sl[i] = (float)sl[i];
        out_tl[i] = (float)tl[i];
    }
}

extern "C" void kernel_launch(void* const* d_in, const int* in_sizes, int n_in,
                              void* d_out, int out_size)
{
    const float* src  = (const float*)d_in[0];   // (B, T, D)
    const int*   sl   = (const int*)  d_in[1];   // (B,)
    const float* tgt  = (const float*)d_in[2];   // (B, U, D)
    const int*   tl   = (const int*)  d_in[3];   // (B,)
    const float* hptr = (const float*)d_in[4];   // (B, T, U, A) == (M, A)
    const float* Wb   = (const float*)d_in[5];   // (D, A)
    const float* bb   = (const float*)d_in[6];   // (D,)
    const float* Wo   = (const float*)d_in[7];   // (V, D)
    const float* bo   = (const float*)d_in[8];   // (V,)

    float* out = (float*)d_out;

    // Output layout (reference tuple flattened in order):
    //   [0, M*V)                       output
    //   [M*V, M*V + B)                 source_lengths
    //   [M*V + B, M*V + 2B)            target_lengths
    //   [M*V + 2B, M*V + 2B + M*D)     activation_out
    const long long OFF_SL  = Mm * Vv;
    const long long OFF_TL  = OFF_SL + Bb;
    const long long OFF_ACT = OFF_TL + Bb;

    float* out_main = out;
    float* out_act  = out + OFF_ACT;

    dim3 blk(256);

    // Kernel 1: act = relu(src + tgt + hptr @ W_bias^T + b_bias)
    dim3 g1(Dd / BN, (unsigned)(Mm / BM));
    gemm_nt_kernel<Aa, 1><<<g1, blk>>>(hptr, Wb, bb, src, tgt, out_act, Dd);

    // Kernel 2: out = act @ W_out^T + b_out   (reads act directly from d_out)
    dim3 g2(Vv / BN, (unsigned)(Mm / BM));
    gemm_nt_kernel<Dd, 0><<<g2, blk>>>(out_act, Wo, bo, nullptr, nullptr, out_main, Vv);

    // Lengths pass-through
    lengths_kernel<<<1, 32>>>(sl, tl, out + OFF_SL, out + OFF_TL);

    (void)in_sizes; (void)n_in; (void)out_size;
}

// round 4
// speedup vs baseline: 1.9515x; 1.9515x over previous
#include <cuda_runtime.h>
#include <cstdint>

// Shapes fixed by reference setup_inputs
static constexpr int Bb = 8, Tt = 256, Uu = 64, Dd = 512, Aa = 256, Vv = 1024;
static constexpr long long Mm = (long long)Bb * Tt * Uu;   // 131072

// pack two fp32's top-16 bits (bf16 truncate) into one bf16x2 word
__device__ __forceinline__ uint32_t pack2hi(float x, float y) {
    return __byte_perm(__float_as_uint(x), __float_as_uint(y), 0x7632);
}
__device__ __forceinline__ float hif(float x) {
    return __uint_as_float(__float_as_uint(x) & 0xFFFF0000u);
}

#define MMA_BF16(c, a, b)                                                        \
    asm volatile(                                                                \
        "mma.sync.aligned.m16n8k16.row.col.f32.bf16.bf16.f32 "                   \
        "{%0,%1,%2,%3}, {%4,%5,%6,%7}, {%8,%9}, {%0,%1,%2,%3};"                  \
        : "+f"((c)[0]), "+f"((c)[1]), "+f"((c)[2]), "+f"((c)[3])                 \
        : "r"((a)[0]), "r"((a)[1]), "r"((a)[2]), "r"((a)[3]),                    \
          "r"((b)[0]), "r"((b)[1]))

// NT GEMM, split-bf16 x3: C[m,n] = sum_k A[m,k]*B[n,k] (both K-contiguous).
// CTA tile 128x128, BK=32, 512 threads = 16 warps in 4(M) x 4(N); warp tile 32x32.
// FUSE=1: C = relu(acc + src[b,t,n] + tgt[b,u,n] + bias[n]); FUSE=0: C = acc + bias[n]
template <int K, int FUSE>
__global__ __launch_bounds__(512)
void mma_gemm(const float* __restrict__ A, const float* __restrict__ B,
              const float* __restrict__ bias,
              const float* __restrict__ src, const float* __restrict__ tgt,
              float* __restrict__ C, int N)
{
    constexpr int BK  = 32;
    constexpr int KB  = K / BK;
    constexpr int S   = 20;        // smem row stride in 32-bit words (bank-spread)
    constexpr int ROW = 128;
    constexpr int ARR = ROW * S;   // 2560 words per array
    constexpr int STG = 4 * ARR;   // Ah, Al, Bh, Bl per stage

    extern __shared__ uint32_t sw[];

    const int tid  = threadIdx.x;
    const int wid  = tid >> 5;
    const int lane = tid & 31;
    const int gid  = lane >> 2;    // 0..7
    const int tig  = lane & 3;     // 0..3
    const int wm   = (wid & 3) * 32;
    const int wn   = (wid >> 2) * 32;
    const long long m0 = (long long)blockIdx.y * 128;
    const int n0 = blockIdx.x * 128;

    float c[2][4][4];
#pragma unroll
    for (int i = 0; i < 2; i++)
#pragma unroll
        for (int j = 0; j < 4; j++)
#pragma unroll
            for (int t = 0; t < 4; t++) c[i][j][t] = 0.0f;

    const float* Ag = A + m0 * K;
    const float* Bg = B + (long long)n0 * K;

    float4 ra[2], rb[2];

    auto g_load = [&](int kb) {
#pragma unroll
        for (int t = 0; t < 2; t++) {
            const int i   = tid + t * 512;   // 0..1023
            const int row = i >> 3;
            const int c4  = i & 7;
            ra[t] = *(const float4*)(Ag + (long long)row * K + kb * BK + c4 * 4);
            rb[t] = *(const float4*)(Bg + (long long)row * K + kb * BK + c4 * 4);
        }
    };

    auto s_store = [&](int buf) {
        uint32_t* base = sw + buf * STG;
#pragma unroll
        for (int t = 0; t < 2; t++) {
            const int i   = tid + t * 512;
            const int row = i >> 3;
            const int c4  = i & 7;
            const int w   = row * S + c4 * 2;
            {   // A
                float4 v = ra[t];
                base[w]     = pack2hi(v.x, v.y);
                base[w + 1] = pack2hi(v.z, v.w);
                base[ARR + w]     = pack2hi(v.x - hif(v.x), v.y - hif(v.y));
                base[ARR + w + 1] = pack2hi(v.z - hif(v.z), v.w - hif(v.w));
            }
            {   // B
                float4 v = rb[t];
                base[2 * ARR + w]     = pack2hi(v.x, v.y);
                base[2 * ARR + w + 1] = pack2hi(v.z, v.w);
                base[3 * ARR + w]     = pack2hi(v.x - hif(v.x), v.y - hif(v.y));
                base[3 * ARR + w + 1] = pack2hi(v.z - hif(v.z), v.w - hif(v.w));
            }
        }
    };

    g_load(0);
    s_store(0);
    __syncthreads();

#pragma unroll 1
    for (int kb = 0; kb < KB; kb++) {
        if (kb + 1 < KB) g_load(kb + 1);

        const uint32_t* AH = sw + (kb & 1) * STG;
        const uint32_t* AL = AH + ARR;
        const uint32_t* BH = AH + 2 * ARR;
        const uint32_t* BL = AH + 3 * ARR;

#pragma unroll
        for (int ks = 0; ks < 2; ks++) {       // two k16 steps per BK=32
            const int kk2 = ks * 8;
            uint32_t ah[2][4], al[2][4], bh[4][2], bl[4][2];
#pragma unroll
            for (int mi = 0; mi < 2; mi++) {
                const int r0 = (wm + mi * 16 + gid) * S + kk2 + tig;
                const int r1 = (wm + mi * 16 + gid + 8) * S + kk2 + tig;
                ah[mi][0] = AH[r0];     ah[mi][1] = AH[r1];
                ah[mi][2] = AH[r0 + 4]; ah[mi][3] = AH[r1 + 4];
                al[mi][0] = AL[r0];     al[mi][1] = AL[r1];
                al[mi][2] = AL[r0 + 4]; al[mi][3] = AL[r1 + 4];
            }
#pragma unroll
            for (int nj = 0; nj < 4; nj++) {
                const int r = (wn + nj * 8 + gid) * S + kk2 + tig;
                bh[nj][0] = BH[r]; bh[nj][1] = BH[r + 4];
                bl[nj][0] = BL[r]; bl[nj][1] = BL[r + 4];
            }
#pragma unroll
            for (int mi = 0; mi < 2; mi++)
#pragma unroll
                for (int nj = 0; nj < 4; nj++) {
                    MMA_BF16(c[mi][nj], al[mi], bh[nj]);   // lo*hi
                    MMA_BF16(c[mi][nj], ah[mi], bl[nj]);   // hi*lo
                    MMA_BF16(c[mi][nj], ah[mi], bh[nj]);   // hi*hi
                }
        }

        if (kb + 1 < KB) s_store((kb + 1) & 1);
        __syncthreads();
    }

    // Epilogue: c regs {0,1}->row gid, {2,3}->row gid+8; cols nj*8 + 2*tig {+0,+1}
#pragma unroll
    for (int mi = 0; mi < 2; mi++) {
#pragma unroll
        for (int half = 0; half < 2; half++) {
            const long long m = m0 + wm + mi * 16 + gid + half * 8;
            const float* srow = nullptr;
            const float* trow = nullptr;
            if (FUSE) {
                const int mi32 = (int)m;
                const int bi = mi32 / (Tt * Uu);
                const int r  = mi32 % (Tt * Uu);
                const int ti = r / Uu;
                const int ui = r % Uu;
                srow = src + (long long)(bi * Tt + ti) * Dd;
                trow = tgt + (long long)(bi * Uu + ui) * Dd;
            }
            float* crow = C + m * N;
#pragma unroll
            for (int nj = 0; nj < 4; nj++) {
                const int n = n0 + wn + nj * 8 + tig * 2;
                float2 bi2 = *(const float2*)(bias + n);
                float vx = c[mi][nj][half * 2 + 0] + bi2.x;
                float vy = c[mi][nj][half * 2 + 1] + bi2.y;
                if (FUSE) {
                    float2 s2 = *(const float2*)(srow + n);
                    float2 t2 = *(const float2*)(trow + n);
                    vx = fmaxf(vx + s2.x + t2.x, 0.0f);
                    vy = fmaxf(vy + s2.y + t2.y, 0.0f);
                }
                *(float2*)(crow + n) = make_float2(vx, vy);
            }
        }
    }
}

// Pass-through of lengths, converted to the float32 output dtype.
__global__ void lengths_kernel(const int* __restrict__ sl, const int* __restrict__ tl,
                               float* __restrict__ out_sl, float* __restrict__ out_tl)
{
    int i = threadIdx.x;
    if (i < Bb) { out_sl[i] = (float)sl[i]; out_tl[i] = (float)tl[i]; }
}

extern "C" void kernel_launch(void* const* d_in, const int* in_sizes, int n_in,
                              void* d_out, int out_size)
{
    const float* src  = (const float*)d_in[0];   // (B, T, D)
    const int*   sl   = (const int*)  d_in[1];   // (B,)
    const float* tgt  = (const float*)d_in[2];   // (B, U, D)
    const int*   tl   = (const int*)  d_in[3];   // (B,)
    const float* hptr = (const float*)d_in[4];   // (B,T,U,A) == (M, A)
    const float* Wb   = (const float*)d_in[5];   // (D, A)
    const float* bb   = (const float*)d_in[6];   // (D,)
    const float* Wo   = (const float*)d_in[7];   // (V, D)
    const float* bo   = (const float*)d_in[8];   // (V,)

    float* out = (float*)d_out;

    // Output layout: [output | source_lengths | target_lengths | activation_out]
    const long long OFF_SL  = Mm * Vv;
    const long long OFF_TL  = OFF_SL + Bb;
    const long long OFF_ACT = OFF_TL + Bb;
    float* out_main = out;
    float* out_act  = out + OFF_ACT;

    const int SMEM = 2 * 4 * 128 * 20 * 4;   // 81920 B: 2 stages x 4 arrays x 128 x 20 words
    cudaFuncSetAttribute((const void*)mma_gemm<Aa, 1>,
                         cudaFuncAttributeMaxDynamicSharedMemorySize, SMEM);
    cudaFuncSetAttribute((const void*)mma_gemm<Dd, 0>,
                         cudaFuncAttributeMaxDynamicSharedMemorySize, SMEM);

    dim3 blk(512);
    // Kernel 1: act = relu(src + tgt + hptr @ Wb^T + bb)
    dim3 g1(Dd / 128, (unsigned)(Mm / 128));
    mma_gemm<Aa, 1><<<g1, blk, SMEM>>>(hptr, Wb, bb, src, tgt, out_act, Dd);
    // Kernel 2: out = act @ Wo^T + bo (act read back from d_out)
    dim3 g2(Vv / 128, (unsigned)(Mm / 128));
    mma_gemm<Dd, 0><<<g2, blk, SMEM>>>(out_act, Wo, bo, nullptr, nullptr, out_main, Vv);

    lengths_kernel<<<1, 32>>>(sl, tl, out + OFF_SL, out + OFF_TL);

    (void)in_sizes; (void)n_in; (void)out_size;
}

// round 5
// speedup vs baseline: 2.1823x; 1.1183x over previous
#include <cuda_runtime.h>
#include <cstdint>

// Shapes fixed by reference setup_inputs
static constexpr int Bb = 8, Tt = 256, Uu = 64, Dd = 512, Aa = 256, Vv = 1024;
static constexpr long long Mm = (long long)Bb * Tt * Uu;   // 131072

// pack two fp32's top-16 bits (bf16 truncate) into one bf16x2 word
__device__ __forceinline__ uint32_t pack2hi(float x, float y) {
    return __byte_perm(__float_as_uint(x), __float_as_uint(y), 0x7632);
}
__device__ __forceinline__ float hif(float x) {
    return __uint_as_float(__float_as_uint(x) & 0xFFFF0000u);
}
__device__ __forceinline__ uint32_t smem_u32(const void* p) {
    uint32_t a;
    asm("{ .reg .u64 t; cvta.to.shared.u64 t, %1; cvt.u32.u64 %0, t; }" : "=r"(a) : "l"(p));
    return a;
}
__device__ __forceinline__ void ldsm4(uint32_t r[4], uint32_t addr) {
    asm volatile("ldmatrix.sync.aligned.m8n8.x4.shared.b16 {%0,%1,%2,%3}, [%4];"
                 : "=r"(r[0]), "=r"(r[1]), "=r"(r[2]), "=r"(r[3]) : "r"(addr));
}

#define MMA_BF16(c, a, b)                                                        \
    asm volatile(                                                                \
        "mma.sync.aligned.m16n8k16.row.col.f32.bf16.bf16.f32 "                   \
        "{%0,%1,%2,%3}, {%4,%5,%6,%7}, {%8,%9}, {%0,%1,%2,%3};"                  \
        : "+f"((c)[0]), "+f"((c)[1]), "+f"((c)[2]), "+f"((c)[3])                 \
        : "r"((a)[0]), "r"((a)[1]), "r"((a)[2]), "r"((a)[3]),                    \
          "r"((b)[0]), "r"((b)[1]))

// NT GEMM, split-bf16 x3: C[m,n] = sum_k A[m,k]*B[n,k] (both K-contiguous).
// CTA tile 128x128, BK=32, 512 threads = 16 warps in 4(M) x 4(N); warp tile 32x32.
// smem: per stage 4 arrays (Ah, Al, Bh, Bl), each 128 rows x 16 bf16x2 words + 4 pad.
// Fragment loads via ldmatrix.x4. FUSE=1 adds src+tgt+bias+ReLU epilogue.
template <int K, int FUSE>
__global__ __launch_bounds__(512)
void mma_gemm(const float* __restrict__ A, const float* __restrict__ B,
              const float* __restrict__ bias,
              const float* __restrict__ src, const float* __restrict__ tgt,
              float* __restrict__ C, int N)
{
    constexpr int BK  = 32;
    constexpr int KB  = K / BK;
    constexpr int S   = 20;            // row stride in 32-bit words (80B, 16B-aligned)
    constexpr int ARR = 128 * S;       // words per array
    constexpr int STG = 4 * ARR;       // Ah, Al, Bh, Bl

    extern __shared__ uint32_t sw[];
    const uint32_t sbase = smem_u32(sw);

    const int tid  = threadIdx.x;
    const int wid  = tid >> 5;
    const int lane = tid & 31;
    const int gid  = lane >> 2;
    const int tig  = lane & 3;
    const int wm   = (wid & 3) * 32;
    const int wn   = (wid >> 2) * 32;
    const long long m0 = (long long)blockIdx.y * 128;
    const int n0 = blockIdx.x * 128;

    // ldmatrix lane addressing (byte offsets within an array)
    const int a_row = ((lane >> 3) & 1) * 8 + (lane & 7);
    const int a_koff = (lane >> 4) * 16;               // bytes
    const int b_row = (lane >> 4) * 8 + (lane & 7);
    const int b_koff = ((lane >> 3) & 1) * 16;         // bytes
    // base byte offset (buf 0) of each lane's ldmatrix row
    const uint32_t aAddr0 = sbase + (wm + a_row) * (S * 4) + a_koff;
    const uint32_t bAddr0 = sbase + (wn + b_row) * (S * 4) + b_koff;

    float c[2][4][4];
#pragma unroll
    for (int i = 0; i < 2; i++)
#pragma unroll
        for (int j = 0; j < 4; j++)
#pragma unroll
            for (int t = 0; t < 4; t++) c[i][j][t] = 0.0f;

    const float* Ag = A + m0 * K;
    const float* Bg = B + (long long)n0 * K;

    float4 ra[2], rb[2];
    const int prow = tid >> 3;          // producer row 0..63 (t adds 64)
    const int pc4  = tid & 7;           // 0..7 -> float4 index within BK

    auto g_load = [&](int kb) {
#pragma unroll
        for (int t = 0; t < 2; t++) {
            const int row = prow + t * 64;
            ra[t] = *(const float4*)(Ag + (long long)row * K + kb * BK + pc4 * 4);
            rb[t] = *(const float4*)(Bg + (long long)row * K + kb * BK + pc4 * 4);
        }
    };

    auto s_store = [&](int buf) {
        uint32_t* base = sw + buf * STG;
#pragma unroll
        for (int t = 0; t < 2; t++) {
            const int row = prow + t * 64;
            const int w   = row * S + pc4 * 2;
            {
                float4 v = ra[t];
                *(uint2*)(base + w) =
                    make_uint2(pack2hi(v.x, v.y), pack2hi(v.z, v.w));
                *(uint2*)(base + ARR + w) =
                    make_uint2(pack2hi(v.x - hif(v.x), v.y - hif(v.y)),
                               pack2hi(v.z - hif(v.z), v.w - hif(v.w)));
            }
            {
                float4 v = rb[t];
                *(uint2*)(base + 2 * ARR + w) =
                    make_uint2(pack2hi(v.x, v.y), pack2hi(v.z, v.w));
                *(uint2*)(base + 3 * ARR + w) =
                    make_uint2(pack2hi(v.x - hif(v.x), v.y - hif(v.y)),
                               pack2hi(v.z - hif(v.z), v.w - hif(v.w)));
            }
        }
    };

    g_load(0);
    s_store(0);
    __syncthreads();

#pragma unroll 1
    for (int kb = 0; kb < KB; kb++) {
        if (kb + 1 < KB) g_load(kb + 1);

        const uint32_t bufb = (kb & 1) * (STG * 4);   // byte offset of stage

#pragma unroll
        for (int ks = 0; ks < 2; ks++) {
            const uint32_t kbyte = ks * 32;
            uint32_t ah[2][4], al[2][4], bh[2][4], bl[2][4];
#pragma unroll
            for (int mi = 0; mi < 2; mi++) {
                const uint32_t a0 = aAddr0 + bufb + mi * (16 * S * 4) + kbyte;
                ldsm4(ah[mi], a0);
                ldsm4(al[mi], a0 + ARR * 4);
            }
#pragma unroll
            for (int p = 0; p < 2; p++) {
                const uint32_t b0 = bAddr0 + bufb + 2 * ARR * 4 + p * (16 * S * 4) + kbyte;
                ldsm4(bh[p], b0);
                ldsm4(bl[p], b0 + ARR * 4);
            }
#pragma unroll
            for (int mi = 0; mi < 2; mi++)
#pragma unroll
                for (int p = 0; p < 2; p++)
#pragma unroll
                    for (int q = 0; q < 2; q++) {
                        MMA_BF16(c[mi][p * 2 + q], al[mi], &bh[p][q * 2]);   // lo*hi
                        MMA_BF16(c[mi][p * 2 + q], ah[mi], &bl[p][q * 2]);   // hi*lo
                        MMA_BF16(c[mi][p * 2 + q], ah[mi], &bh[p][q * 2]);   // hi*hi
                    }
        }

        if (kb + 1 < KB) s_store((kb + 1) & 1);
        __syncthreads();
    }

    // Epilogue: acc c[mi][nj][t]: rows gid/gid+8, cols nj*8 + 2*tig (+1)
#pragma unroll
    for (int mi = 0; mi < 2; mi++) {
#pragma unroll
        for (int half = 0; half < 2; half++) {
            const long long m = m0 + wm + mi * 16 + gid + half * 8;
            const float* srow = nullptr;
            const float* trow = nullptr;
            if (FUSE) {
                const int mi32 = (int)m;
                const int bi = mi32 / (Tt * Uu);
                const int r  = mi32 % (Tt * Uu);
                const int ti = r / Uu;
                const int ui = r % Uu;
                srow = src + (long long)(bi * Tt + ti) * Dd;
                trow = tgt + (long long)(bi * Uu + ui) * Dd;
            }
            float* crow = C + m * N;
#pragma unroll
            for (int nj = 0; nj < 4; nj++) {
                const int n = n0 + wn + nj * 8 + tig * 2;
                float2 bi2 = *(const float2*)(bias + n);
                float vx = c[mi][nj][half * 2 + 0] + bi2.x;
                float vy = c[mi][nj][half * 2 + 1] + bi2.y;
                if (FUSE) {
                    float2 s2 = *(const float2*)(srow + n);
                    float2 t2 = *(const float2*)(trow + n);
                    vx = fmaxf(vx + s2.x + t2.x, 0.0f);
                    vy = fmaxf(vy + s2.y + t2.y, 0.0f);
                }
                *(float2*)(crow + n) = make_float2(vx, vy);
            }
        }
    }
}

// Pass-through of lengths, converted to the float32 output dtype.
__global__ void lengths_kernel(const int* __restrict__ sl, const int* __restrict__ tl,
                               float* __restrict__ out_sl, float* __restrict__ out_tl)
{
    int i = threadIdx.x;
    if (i < Bb) { out_sl[i] = (float)sl[i]; out_tl[i] = (float)tl[i]; }
}

extern "C" void kernel_launch(void* const* d_in, const int* in_sizes, int n_in,
                              void* d_out, int out_size)
{
    const float* src  = (const float*)d_in[0];   // (B, T, D)
    const int*   sl   = (const int*)  d_in[1];   // (B,)
    const float* tgt  = (const float*)d_in[2];   // (B, U, D)
    const int*   tl   = (const int*)  d_in[3];   // (B,)
    const float* hptr = (const float*)d_in[4];   // (B,T,U,A) == (M, A)
    const float* Wb   = (const float*)d_in[5];   // (D, A)
    const float* bb   = (const float*)d_in[6];   // (D,)
    const float* Wo   = (const float*)d_in[7];   // (V, D)
    const float* bo   = (const float*)d_in[8];   // (V,)

    float* out = (float*)d_out;

    // Output layout: [output | source_lengths | target_lengths | activation_out]
    const long long OFF_SL  = Mm * Vv;
    const long long OFF_TL  = OFF_SL + Bb;
    const long long OFF_ACT = OFF_TL + Bb;
    float* out_main = out;
    float* out_act  = out + OFF_ACT;

    const int SMEM = 2 * 4 * 128 * 20 * 4;   // 81920 B
    cudaFuncSetAttribute((const void*)mma_gemm<Aa, 1>,
                         cudaFuncAttributeMaxDynamicSharedMemorySize, SMEM);
    cudaFuncSetAttribute((const void*)mma_gemm<Dd, 0>,
                         cudaFuncAttributeMaxDynamicSharedMemorySize, SMEM);

    dim3 blk(512);
    // Kernel 1: act = relu(src + tgt + hptr @ Wb^T + bb)
    dim3 g1(Dd / 128, (unsigned)(Mm / 128));
    mma_gemm<Aa, 1><<<g1, blk, SMEM>>>(hptr, Wb, bb, src, tgt, out_act, Dd);
    // Kernel 2: out = act @ Wo^T + bo (act read back from d_out)
    dim3 g2(Vv / 128, (unsigned)(Mm / 128));
    mma_gemm<Dd, 0><<<g2, blk, SMEM>>>(out_act, Wo, bo, nullptr, nullptr, out_main, Vv);

    lengths_kernel<<<1, 32>>>(sl, tl, out + OFF_SL, out + OFF_TL);

    (void)in_sizes; (void)n_in; (void)out_size;
}